// round 5
// baseline (speedup 1.0000x reference)
#include <cuda_runtime.h>
#include <cstdint>

#define Bk 128
#define Sk 128
#define Ek 256
#define Dk 512
#define Kk 16
#define Lk 1906
#define Rk 2033
#define Tk 127
#define TINYF 1.17549435e-38f

__device__ float g_h[2][Bk][Dk];
__device__ float g_x[Bk][Dk];
__device__ float g_last_t[Bk];
__device__ int   g_last_m[Bk];
__device__ int   g_chosen[Bk];
__device__ int   g_cand[Bk][Lk];
__device__ float g_prob[Bk][Lk];
__device__ float g_nrec[Bk][Rk];
__device__ unsigned g_cnt[4][32];   // per-group counters, 128B apart

// transposed weights: wT[d][e] = W[e*ldW + d]
__device__ float wTel[Dk][Ek];
__device__ float wTih[Dk][Dk];
__device__ float wThh[Dk][Dk];

// JAX threefry2x32 (exact)
__device__ __forceinline__ void tf2x32(uint32_t k0, uint32_t k1,
                                       uint32_t x0, uint32_t x1,
                                       uint32_t& o0, uint32_t& o1) {
  uint32_t ks2 = k0 ^ k1 ^ 0x1BD11BDAu;
  x0 += k0; x1 += k1;
#define RR(d) { x0 += x1; x1 = (x1 << d) | (x1 >> (32 - d)); x1 ^= x0; }
  RR(13) RR(15) RR(26) RR(6)  x0 += k1;  x1 += ks2 + 1u;
  RR(17) RR(29) RR(16) RR(24) x0 += ks2; x1 += k0 + 2u;
  RR(13) RR(15) RR(26) RR(6)  x0 += k0;  x1 += k1 + 3u;
  RR(17) RR(29) RR(16) RR(24) x0 += k1;  x1 += ks2 + 4u;
  RR(13) RR(15) RR(26) RR(6)  x0 += ks2; x1 += k0 + 5u;
#undef RR
  o0 = x0; o1 = x1;
}

__global__ void reset_kernel() {
  if (threadIdx.x < 128) ((unsigned*)g_cnt)[threadIdx.x] = 0u;
}

// 32x32 tile transpose of the three weight matrices
__global__ void transpose_kernel(const float* __restrict__ Wel,
                                 const float* __restrict__ Wih,
                                 const float* __restrict__ Whh) {
  __shared__ float tile[32][33];
  int z = blockIdx.z;
  const float* src = (z == 0) ? Wel : (z == 1) ? Wih : Whh;
  int R = (z == 0) ? Ek : Dk;            // source rows (e-dim)
  int r0 = blockIdx.y * 32, c0 = blockIdx.x * 32;
  if (r0 >= R) return;
  int tx = threadIdx.x & 31, ty = threadIdx.x >> 5;  // 32x8
#pragma unroll
  for (int i = 0; i < 32; i += 8)
    tile[ty + i][tx] = src[(size_t)(r0 + ty + i) * Dk + c0 + tx];
  __syncthreads();
  float* dst = (z == 0) ? &wTel[0][0] : (z == 1) ? &wTih[0][0] : &wThh[0][0];
  int ds = (z == 0) ? Ek : Dk;
#pragma unroll
  for (int i = 0; i < 32; i += 8)
    dst[(size_t)(c0 + ty + i) * ds + r0 + tx] = tile[tx][ty + i];
}

// fence-free group barrier: release-atomic arrive + acquire-poll (no CCTL.IVALL)
__device__ __forceinline__ void gbar(int bc, unsigned& epoch) {
  __syncthreads();
  if (threadIdx.x == 0) {
    epoch += 32u;
    unsigned old;
    asm volatile("atom.add.release.gpu.u32 %0, [%1], %2;"
                 : "=r"(old) : "l"(&g_cnt[bc][0]), "r"(1u) : "memory");
    unsigned v;
    do {
      asm volatile("ld.acquire.gpu.u32 %0, [%1];"
                   : "=r"(v) : "l"(&g_cnt[bc][0]) : "memory");
    } while (v < epoch);
  }
  __syncthreads();
}

__global__ void __launch_bounds__(256, 1)
rnn_persistent(const int* __restrict__ marker,
               const float* __restrict__ timed,
               const float* __restrict__ maskd,
               const float* __restrict__ emb,
               const int* __restrict__ nlist,
               const float* __restrict__ nprob,
               const float* __restrict__ W_te,
               const float* __restrict__ b_te,
               const float* __restrict__ b_el,
               const float* __restrict__ b_ih,
               const float* __restrict__ b_hh,
               const float* __restrict__ W_time,
               const float* __restrict__ b_time,
               const float* __restrict__ W_mk,
               const float* __restrict__ b_mk,
               float* __restrict__ out) {
  __shared__ __align__(16) float SM[8704];
  const int BID = blockIdx.x;
  const int tid = threadIdx.x;
  const int bc = BID >> 5;    // group (32 batch rows)
  const int dc = BID & 31;    // d tile (16 cols)
  const int myb = BID;        // phase-C row
  unsigned epoch = 0;

  // ---------------- init (each block its own row) ----------------
  for (int l = tid; l < Lk; l += 256) {
    g_prob[myb][l] = (l == 0) ? 1.0f : 0.0f;
    g_cand[myb][l] = (l == 0) ? marker[myb * Sk] : 0;
  }
  for (int r = tid; r < Rk; r += 256) g_nrec[myb][r] = 1.0f;
  for (int d = tid; d < Dk; d += 256) __stcg(&g_h[0][myb][d], 0.0f);
  if (tid == 0) {
    __stcg(&g_last_t[myb], timed[myb * Sk]);
    __stcg(&g_last_m[myb], marker[myb * Sk]);
    g_chosen[myb] = 0;
    out[0 * 16384 + myb * Sk] = (float)marker[myb * Sk];
    out[1 * 16384 + myb * Sk] = timed[myb * Sk];
    out[2 * 16384 + myb * Sk] = maskd[myb * Sk];
    out[3 * 16384 + myb * Sk] = 1.0f;
    out[4 * 16384 + myb * Sk] = 1.0f;
  }
  gbar(bc, epoch);

  for (int t = 0; t < Tk; t++) {
    // ============ Phase A: x = leaky(vec @ W_el + b_el) ============
    {
      float* sV = SM;                       // [32][260]
      float* sLt = SM + 8320;               // [32]
      int*   sLm = (int*)(SM + 8352);       // [32]
      if (tid < 32) {
        sLt[tid] = __ldcg(&g_last_t[bc * 32 + tid]);
        sLm[tid] = __ldcg(&g_last_m[bc * 32 + tid]);
      }
      __syncthreads();
      int e = tid;
      float wte = W_te[e], bte = b_te[e];
#pragma unroll 4
      for (int bl = 0; bl < 32; bl++) {
        float te = __fadd_rn(__fmul_rn(sLt[bl], wte), bte);
        sV[bl * 260 + e] = __fadd_rn(emb[(size_t)sLm[bl] * Ek + e],
                                     __fmul_rn(0.1f, te));
      }
      __syncthreads();
      int dl = tid & 15, bh = tid >> 4;
      int d = dc * 16 + dl;
      const float4* wp4 = (const float4*)&wTel[d][0];
      const float4* v04 = (const float4*)(sV + bh * 260);
      const float4* v14 = (const float4*)(sV + (bh + 16) * 260);
      float a0 = 0.0f, a1 = 0.0f;
#pragma unroll 8
      for (int e4 = 0; e4 < Ek / 4; e4++) {
        float4 w = wp4[e4];
        float4 x0 = v04[e4];
        float4 x1 = v14[e4];
        a0 = fmaf(x0.x, w.x, a0); a1 = fmaf(x1.x, w.x, a1);
        a0 = fmaf(x0.y, w.y, a0); a1 = fmaf(x1.y, w.y, a1);
        a0 = fmaf(x0.z, w.z, a0); a1 = fmaf(x1.z, w.z, a1);
        a0 = fmaf(x0.w, w.w, a0); a1 = fmaf(x1.w, w.w, a1);
      }
      float bb = b_el[d];
      a0 = __fadd_rn(a0, bb);
      a1 = __fadd_rn(a1, bb);
      __stcg(&g_x[bc * 32 + bh][d],      (a0 >= 0.0f) ? a0 : __fmul_rn(0.01f, a0));
      __stcg(&g_x[bc * 32 + bh + 16][d], (a1 >= 0.0f) ? a1 : __fmul_rn(0.01f, a1));
    }
    gbar(bc, epoch);

    // ============ Phase B: h = tanh(x@W_ih + b_ih + h@W_hh + b_hh) ============
    {
      float* sx = SM;                 // [32][132]
      float* sh = SM + 32 * 132;      // [32][132]
      const float* hin = &g_h[t & 1][0][0];
      int dp = tid & 7, bl = tid >> 3;
      int b = bc * 32 + bl;
      int d0 = dc * 16 + dp * 2;
      float ax0 = 0, ax1 = 0, ah0 = 0, ah1 = 0;
      for (int ch = 0; ch < 4; ch++) {
        __syncthreads();
        {
          // stage 32x128 of x and h via L2 (cross-SM fresh)
          int i = tid * 4;
          int r = i >> 7, c = i & 127;
#pragma unroll
          for (int k = 0; k < 4; k++) {
            float4 xv = __ldcg((const float4*)&g_x[bc * 32 + r][ch * 128 + c]);
            float4 hv = __ldcg((const float4*)&hin[(bc * 32 + r) * Dk + ch * 128 + c]);
            *(float4*)&sx[r * 132 + c] = xv;
            *(float4*)&sh[r * 132 + c] = hv;
            r += 8;
          }
        }
        __syncthreads();
        const float4* wi0 = (const float4*)&wTih[d0][ch * 128];
        const float4* wi1 = (const float4*)&wTih[d0 + 1][ch * 128];
        const float4* wh0 = (const float4*)&wThh[d0][ch * 128];
        const float4* wh1 = (const float4*)&wThh[d0 + 1][ch * 128];
        const float4* px = (const float4*)(sx + bl * 132);
        const float4* ph = (const float4*)(sh + bl * 132);
#pragma unroll 4
        for (int e4 = 0; e4 < 32; e4++) {
          float4 xv = px[e4];
          float4 hv = ph[e4];
          float4 a = wi0[e4], b2 = wi1[e4], c2 = wh0[e4], d2 = wh1[e4];
          ax0 = fmaf(xv.x, a.x, ax0); ax1 = fmaf(xv.x, b2.x, ax1);
          ah0 = fmaf(hv.x, c2.x, ah0); ah1 = fmaf(hv.x, d2.x, ah1);
          ax0 = fmaf(xv.y, a.y, ax0); ax1 = fmaf(xv.y, b2.y, ax1);
          ah0 = fmaf(hv.y, c2.y, ah0); ah1 = fmaf(hv.y, d2.y, ah1);
          ax0 = fmaf(xv.z, a.z, ax0); ax1 = fmaf(xv.z, b2.z, ax1);
          ah0 = fmaf(hv.z, c2.z, ah0); ah1 = fmaf(hv.z, d2.z, ah1);
          ax0 = fmaf(xv.w, a.w, ax0); ax1 = fmaf(xv.w, b2.w, ax1);
          ah0 = fmaf(hv.w, c2.w, ah0); ah1 = fmaf(hv.w, d2.w, ah1);
        }
      }
      float bi0 = b_ih[d0], bi1 = b_ih[d0 + 1];
      float bh0 = b_hh[d0], bh1 = b_hh[d0 + 1];
      float* hout = &g_h[(t + 1) & 1][0][0];
      __stcg(&hout[b * Dk + d0],
             tanhf(__fadd_rn(__fadd_rn(__fadd_rn(ax0, bi0), ah0), bh0)));
      __stcg(&hout[b * Dk + d0 + 1],
             tanhf(__fadd_rn(__fadd_rn(__fadd_rn(ax1, bi1), ah1), bh1)));
    }
    gbar(bc, epoch);

    // ============ Phase C: sampling step for row myb ============
    {
      float* sE = SM;                     // [16][256]
      float* hb = SM + 4096;              // [512]
      float* red = SM + 4608;             // [8]
      float* redv = SM + 4624;            // [8]
      int*   ri   = (int*)(SM + 4640);    // [8]
      int*   s_neigh = (int*)(SM + 4656); // [16]
      float* s_score = SM + 4672;         // [16]
      int warp = tid >> 5, lane = tid & 31;

      hb[tid]       = __ldcg(&g_h[(t + 1) & 1][myb][tid]);
      hb[tid + 256] = __ldcg(&g_h[(t + 1) & 1][myb][tid + 256]);
      int lm = g_last_m[myb];
      if (tid < Kk) {
        s_neigh[tid] = nlist[lm * Kk + tid];
        g_nrec[myb][1 + t * Kk + tid] = nprob[lm * Kk + tid];
      }
      __syncthreads();

      // stage emb rows of the 16 neighbors (immutable -> L1)
      {
        int e = tid;
#pragma unroll 4
        for (int k = 0; k < Kk; k++)
          sE[k * 256 + e] = emb[(size_t)s_neigh[k] * Ek + e];
      }

      // dt partial + warp reduce
      {
        float a = __fmul_rn(hb[2 * tid], W_time[2 * tid]);
        a = fmaf(hb[2 * tid + 1], W_time[2 * tid + 1], a);
        for (int o = 16; o; o >>= 1) a = __fadd_rn(a, __shfl_down_sync(0xffffffffu, a, o));
        if (lane == 0) red[warp] = a;
      }
      __syncthreads();

      // neighbor scores: dot([emb[neigh], h], W_mk) + b_mk (len 768)
      for (int k = warp; k < Kk; k += 8) {
        const float* ev = sE + k * 256;
        float acc = 0.0f;
        for (int i = lane; i < Ek + Dk; i += 32) {
          float v = (i < Ek) ? ev[i] : hb[i - Ek];
          acc = fmaf(v, W_mk[i], acc);
        }
        for (int o = 16; o; o >>= 1) acc += __shfl_down_sync(0xffffffffu, acc, o);
        if (lane == 0) s_score[k] = __fadd_rn(acc, b_mk[0]);
      }

      float newt = 0.0f;
      if (tid == 0) {
        float s = red[0];
        for (int w = 1; w < 8; w++) s = __fadd_rn(s, red[w]);
        float xx = __fadd_rn(s, b_time[0]);
        float sp = __fadd_rn(fmaxf(xx, 0.0f), log1pf(expf(-fabsf(xx))));
        newt = __fadd_rn(g_last_t[myb], sp);
      }
      __syncthreads();

      if (tid == 0) {
        float mx = s_score[0];
        for (int k = 1; k < Kk; k++) mx = fmaxf(mx, s_score[k]);
        float ee[Kk]; float ssum = 0.0f;
        for (int k = 0; k < Kk; k++) {
          ee[k] = expf(__fadd_rn(s_score[k], -mx));
          ssum = __fadd_rn(ssum, ee[k]);
        }
        int ch = g_chosen[myb];
        float cp = g_prob[myb][ch];
        g_prob[myb][ch] = __fmul_rn(cp, __fdiv_rn(ee[0], ssum));
        int base = 1 + t * (Kk - 1);
        for (int k = 1; k < Kk; k++) {
          g_prob[myb][base + k - 1] = __fmul_rn(cp, __fdiv_rn(ee[k], ssum));
          g_cand[myb][base + k - 1] = s_neigh[k];
        }
      }
      __syncthreads();

      // gumbel-max over the active prefix (prob==0 beyond -> exactly -1e30)
      uint32_t k0, k1;
      tf2x32(0u, 42u, 0u, (uint32_t)t, k0, k1);
      int active = 15 * t + 16;
      if (active > Lk) active = Lk;
      float bv = -3.4e38f; int bi = 0x7fffffff;
      for (int l = tid; l < active; l += 256) {
        float pr = g_prob[myb][l];
        float logit = (pr > 0.0f) ? logf(fmaxf(pr, 1e-38f)) : -1e30f;
        uint32_t i = (uint32_t)(myb * Lk + l);
        uint32_t o0, o1;
        tf2x32(k0, k1, 0u, i, o0, o1);
        uint32_t bits = o0 ^ o1;
        float u0 = __fadd_rn(__uint_as_float((bits >> 9) | 0x3f800000u), -1.0f);
        float u = fmaxf(TINYF, __fadd_rn(u0, TINYF));
        float gq = -logf(-logf(u));
        float v = __fadd_rn(logit, gq);
        if (v > bv) { bv = v; bi = l; }
      }
      for (int o = 16; o; o >>= 1) {
        float ov = __shfl_down_sync(0xffffffffu, bv, o);
        int   oi = __shfl_down_sync(0xffffffffu, bi, o);
        if (ov > bv || (ov == bv && oi < bi)) { bv = ov; bi = oi; }
      }
      if (lane == 0) { redv[warp] = bv; ri[warp] = bi; }
      __syncthreads();

      if (tid == 0) {
        float bestv = redv[0]; int besti = ri[0];
        for (int w = 1; w < 8; w++) {
          if (redv[w] > bestv || (redv[w] == bestv && ri[w] < besti)) {
            bestv = redv[w]; besti = ri[w];
          }
        }
        int nm = g_cand[myb][besti];
        float snp = g_nrec[myb][besti];
        float ssp = g_prob[myb][besti];
        int col = t + 1;
        out[0 * 16384 + myb * Sk + col] = (float)nm;
        out[1 * 16384 + myb * Sk + col] = newt;
        out[2 * 16384 + myb * Sk + col] = (newt < 1000.0f) ? 1.0f : 0.0f;
        out[3 * 16384 + myb * Sk + col] = snp;
        out[4 * 16384 + myb * Sk + col] = ssp;
        g_chosen[myb] = besti;
        __stcg(&g_last_m[myb], nm);
        __stcg(&g_last_t[myb], newt);
      }
    }
    gbar(bc, epoch);
  }
}

extern "C" void kernel_launch(void* const* d_in, const int* in_sizes, int n_in,
                              void* d_out, int out_size) {
  const int*   marker = (const int*)d_in[0];
  const float* timed  = (const float*)d_in[1];
  const float* maskd  = (const float*)d_in[2];
  const float* emb    = (const float*)d_in[3];
  const int*   nlist  = (const int*)d_in[4];
  const float* nprob  = (const float*)d_in[5];
  const float* W_te   = (const float*)d_in[6];
  const float* b_te   = (const float*)d_in[7];
  const float* W_el   = (const float*)d_in[8];
  const float* b_el   = (const float*)d_in[9];
  const float* W_ih   = (const float*)d_in[10];
  const float* b_ih   = (const float*)d_in[11];
  const float* W_hh   = (const float*)d_in[12];
  const float* b_hh   = (const float*)d_in[13];
  const float* W_time = (const float*)d_in[14];
  const float* b_time = (const float*)d_in[15];
  const float* W_mk   = (const float*)d_in[16];
  const float* b_mk   = (const float*)d_in[17];
  float* out = (float*)d_out;

  transpose_kernel<<<dim3(16, 16, 3), 256>>>(W_el, W_ih, W_hh);
  reset_kernel<<<1, 128>>>();
  rnn_persistent<<<128, 256>>>(marker, timed, maskd, emb, nlist, nprob,
                               W_te, b_te, b_el, b_ih, b_hh,
                               W_time, b_time, W_mk, b_mk, out);
}

// round 6
// speedup vs baseline: 3.0013x; 3.0013x over previous
#include <cuda_runtime.h>
#include <cstdint>

#define Bk 128
#define Sk 128
#define Ek 256
#define Dk 512
#define Kk 16
#define Lk 1906
#define Rk 2033
#define Tk 127
#define TINYF 1.17549435e-38f

// smem layout (float offsets)
#define OFF_SCR 0          // scratch: sx[32][260] + sh[32][260] = 16640
#define OFF_SH  8320
#define OFF_WA  16640      // 256e x 8dp float2 = 4096
#define OFF_WBI 20736      // 8dp rows x 514 pairs = 8224
#define OFF_WBH 28960      // 8224
#define OFF_SP  37184      // prob[1906]
#define OFF_SC  39090      // cand[1906] (int)
#define OFF_SN  40996      // nrec[2033]
#define OFF_SLT 43040      // last_t[32]
#define OFF_SLM 43072      // last_m[32]
#define SM_FLOATS 43104
#define SM_BYTES (SM_FLOATS * 4)

__device__ float g_h[2][Bk][Dk];
__device__ float g_x[Bk][Dk];
__device__ float g_last_t[Bk];
__device__ int   g_last_m[Bk];
__device__ unsigned g_cnt[4][32];   // per-group counters, 128B apart

// JAX threefry2x32 (exact)
__device__ __forceinline__ void tf2x32(uint32_t k0, uint32_t k1,
                                       uint32_t x0, uint32_t x1,
                                       uint32_t& o0, uint32_t& o1) {
  uint32_t ks2 = k0 ^ k1 ^ 0x1BD11BDAu;
  x0 += k0; x1 += k1;
#define RR(d) { x0 += x1; x1 = (x1 << d) | (x1 >> (32 - d)); x1 ^= x0; }
  RR(13) RR(15) RR(26) RR(6)  x0 += k1;  x1 += ks2 + 1u;
  RR(17) RR(29) RR(16) RR(24) x0 += ks2; x1 += k0 + 2u;
  RR(13) RR(15) RR(26) RR(6)  x0 += k0;  x1 += k1 + 3u;
  RR(17) RR(29) RR(16) RR(24) x0 += k1;  x1 += ks2 + 4u;
  RR(13) RR(15) RR(26) RR(6)  x0 += ks2; x1 += k0 + 5u;
#undef RR
  o0 = x0; o1 = x1;
}

__device__ __forceinline__ unsigned long long dup2(float v) {
  unsigned long long r;
  asm("mov.b64 %0, {%1, %1};" : "=l"(r) : "f"(v));
  return r;
}
__device__ __forceinline__ void ffma2(unsigned long long& acc,
                                      unsigned long long a,
                                      unsigned long long b) {
  asm("fma.rn.f32x2 %0, %1, %2, %3;" : "=l"(acc) : "l"(a), "l"(b), "l"(acc));
}

__global__ void reset_kernel() {
  if (threadIdx.x < 128) ((unsigned*)g_cnt)[threadIdx.x] = 0u;
}

// R4-proven group barrier: fence + atomic arrive + volatile poll + fence
__device__ __forceinline__ void gbar(int bc, unsigned& epoch) {
  __syncthreads();
  if (threadIdx.x == 0) {
    __threadfence();
    epoch += 32u;
    atomicAdd(&g_cnt[bc][0], 1u);
    while (*((volatile unsigned*)&g_cnt[bc][0]) < epoch) { }
    __threadfence();
  }
  __syncthreads();
}

__global__ void __launch_bounds__(256, 1)
rnn_persistent(const int* __restrict__ marker,
               const float* __restrict__ timed,
               const float* __restrict__ maskd,
               const float* __restrict__ emb,
               const int* __restrict__ nlist,
               const float* __restrict__ nprob,
               const float* __restrict__ W_te,
               const float* __restrict__ b_te,
               const float* __restrict__ W_el,
               const float* __restrict__ b_el,
               const float* __restrict__ W_ih,
               const float* __restrict__ b_ih,
               const float* __restrict__ W_hh,
               const float* __restrict__ b_hh,
               const float* __restrict__ W_time,
               const float* __restrict__ b_time,
               const float* __restrict__ W_mk,
               const float* __restrict__ b_mk,
               float* __restrict__ out) {
  extern __shared__ __align__(16) float SM[];
  const int BID = blockIdx.x;
  const int tid = threadIdx.x;
  const int bc = BID >> 5;    // group (32 batch rows)
  const int dc = BID & 31;    // d tile (16 cols)
  const int myb = BID;        // phase-C row
  unsigned epoch = 0;

  float* sP = SM + OFF_SP;
  int*   sC = (int*)(SM + OFF_SC);
  float* sN = SM + OFF_SN;

  // ---------------- one-time init ----------------
  // weight tiles into smem (per block)
  for (int i = tid; i < Ek * 8; i += 256) {
    int e = i >> 3, dp = i & 7;
    ((float2*)(SM + OFF_WA))[e * 8 + dp] =
        *(const float2*)&W_el[e * Dk + dc * 16 + dp * 2];
  }
  for (int i = tid; i < Dk * 8; i += 256) {
    int e = i >> 3, dp = i & 7;
    ((float2*)(SM + OFF_WBI))[dp * 514 + e] =
        *(const float2*)&W_ih[e * Dk + dc * 16 + dp * 2];
    ((float2*)(SM + OFF_WBH))[dp * 514 + e] =
        *(const float2*)&W_hh[e * Dk + dc * 16 + dp * 2];
  }
  // block-private sampling state
  for (int l = tid; l < Lk; l += 256) {
    sP[l] = (l == 0) ? 1.0f : 0.0f;
    sC[l] = (l == 0) ? marker[myb * Sk] : 0;
  }
  for (int r = tid; r < Rk; r += 256) sN[r] = 1.0f;
  for (int d = tid; d < Dk; d += 256) g_h[0][myb][d] = 0.0f;
  int chosen = 0;  // uniform across block (only tid0 uses it meaningfully)
  if (tid == 0) {
    g_last_t[myb] = timed[myb * Sk];
    g_last_m[myb] = marker[myb * Sk];
    out[0 * 16384 + myb * Sk] = (float)marker[myb * Sk];
    out[1 * 16384 + myb * Sk] = timed[myb * Sk];
    out[2 * 16384 + myb * Sk] = maskd[myb * Sk];
    out[3 * 16384 + myb * Sk] = 1.0f;
    out[4 * 16384 + myb * Sk] = 1.0f;
  }
  gbar(bc, epoch);

  const int dp = tid & 7;
  const int blw = tid >> 3;           // 0..31
  const int d0 = dc * 16 + dp * 2;
  const int bg = bc * 32 + blw;

  for (int t = 0; t < Tk; t++) {
    // ============ Phase A: x = leaky(vec @ W_el + b_el) ============
    {
      float* sV = SM + OFF_SCR;  // [32][260]
      if (tid < 32) {
        SM[OFF_SLT + tid] = g_last_t[bc * 32 + tid];
        ((int*)(SM + OFF_SLM))[tid] = g_last_m[bc * 32 + tid];
      }
      __syncthreads();
      {
        int e = tid;
        float wte = W_te[e], bte = b_te[e];
#pragma unroll 4
        for (int bl = 0; bl < 32; bl++) {
          float te = __fadd_rn(__fmul_rn(SM[OFF_SLT + bl], wte), bte);
          sV[bl * 260 + e] =
              __fadd_rn(emb[(size_t)((int*)(SM + OFF_SLM))[bl] * Ek + e],
                        __fmul_rn(0.1f, te));
        }
      }
      __syncthreads();
      const float* pv = sV + blw * 260;
      const float2* wa = (const float2*)(SM + OFF_WA);
      float a0 = 0.0f, a1 = 0.0f;
#pragma unroll 8
      for (int e = 0; e < Ek; e++) {
        float v = pv[e];
        float2 w = wa[e * 8 + dp];
        a0 = fmaf(v, w.x, a0);
        a1 = fmaf(v, w.y, a1);
      }
      a0 = __fadd_rn(a0, b_el[d0]);
      a1 = __fadd_rn(a1, b_el[d0 + 1]);
      float2 r;
      r.x = (a0 >= 0.0f) ? a0 : __fmul_rn(0.01f, a0);
      r.y = (a1 >= 0.0f) ? a1 : __fmul_rn(0.01f, a1);
      *(float2*)&g_x[bg][d0] = r;
    }
    gbar(bc, epoch);

    // ============ Phase B: h = tanh(x@W_ih + b_ih + h@W_hh + b_hh) ============
    {
      const float* hin = &g_h[t & 1][0][0];
      unsigned long long axx = 0ull, ahh = 0ull;
      for (int c = 0; c < 2; c++) {
        __syncthreads();
        for (int i = tid; i < 32 * 64; i += 256) {
          int r = i >> 6, cc = (i & 63) << 2;
          *(float4*)&SM[OFF_SCR + r * 260 + cc] =
              *(const float4*)&g_x[bc * 32 + r][c * 256 + cc];
          *(float4*)&SM[OFF_SH + r * 260 + cc] =
              *(const float4*)&hin[(bc * 32 + r) * Dk + c * 256 + cc];
        }
        __syncthreads();
        const float4* px = (const float4*)(SM + OFF_SCR + blw * 260);
        const float4* ph = (const float4*)(SM + OFF_SH + blw * 260);
        const ulonglong2* pwi =
            (const ulonglong2*)(SM + OFF_WBI) + (dp * 257 + c * 128);
        const ulonglong2* pwh =
            (const ulonglong2*)(SM + OFF_WBH) + (dp * 257 + c * 128);
#pragma unroll 8
        for (int e4 = 0; e4 < 64; e4++) {
          float4 xq = px[e4];
          float4 hq = ph[e4];
          ulonglong2 wiA = pwi[2 * e4], wiB = pwi[2 * e4 + 1];
          ulonglong2 whA = pwh[2 * e4], whB = pwh[2 * e4 + 1];
          ffma2(axx, dup2(xq.x), wiA.x); ffma2(ahh, dup2(hq.x), whA.x);
          ffma2(axx, dup2(xq.y), wiA.y); ffma2(ahh, dup2(hq.y), whA.y);
          ffma2(axx, dup2(xq.z), wiB.x); ffma2(ahh, dup2(hq.z), whB.x);
          ffma2(axx, dup2(xq.w), wiB.y); ffma2(ahh, dup2(hq.w), whB.y);
        }
      }
      float ax0, ax1, ah0, ah1;
      asm("mov.b64 {%0, %1}, %2;" : "=f"(ax0), "=f"(ax1) : "l"(axx));
      asm("mov.b64 {%0, %1}, %2;" : "=f"(ah0), "=f"(ah1) : "l"(ahh));
      float2 r;
      r.x = tanhf(__fadd_rn(__fadd_rn(__fadd_rn(ax0, b_ih[d0]), ah0), b_hh[d0]));
      r.y = tanhf(__fadd_rn(__fadd_rn(__fadd_rn(ax1, b_ih[d0 + 1]), ah1), b_hh[d0 + 1]));
      *(float2*)&g_h[(t + 1) & 1][bg][d0] = r;
    }
    gbar(bc, epoch);

    // ============ Phase C: sampling step for row myb ============
    {
      float* sE = SM + OFF_SCR;            // [16][256]
      float* hb = SM + OFF_SCR + 4096;     // [512]
      float* red  = SM + OFF_SCR + 4608;   // [8]
      float* redv = SM + OFF_SCR + 4624;   // [8]
      int*   ri   = (int*)(SM + OFF_SCR + 4640);   // [8]
      int*   s_neigh = (int*)(SM + OFF_SCR + 4656);// [16]
      float* s_score = SM + OFF_SCR + 4672;        // [16]
      int warp = tid >> 5, lane = tid & 31;

      hb[tid]       = g_h[(t + 1) & 1][myb][tid];
      hb[tid + 256] = g_h[(t + 1) & 1][myb][tid + 256];
      int lm = g_last_m[myb];
      if (tid < Kk) {
        s_neigh[tid] = nlist[lm * Kk + tid];
        sN[1 + t * Kk + tid] = nprob[lm * Kk + tid];
      }
      __syncthreads();

      // stage emb rows of the 16 neighbors
      {
        int e = tid;
#pragma unroll 4
        for (int k = 0; k < Kk; k++)
          sE[k * 256 + e] = emb[(size_t)s_neigh[k] * Ek + e];
      }

      // dt partial + warp reduce
      {
        float a = __fmul_rn(hb[2 * tid], W_time[2 * tid]);
        a = fmaf(hb[2 * tid + 1], W_time[2 * tid + 1], a);
        for (int o = 16; o; o >>= 1)
          a = __fadd_rn(a, __shfl_down_sync(0xffffffffu, a, o));
        if (lane == 0) red[warp] = a;
      }
      __syncthreads();

      // neighbor scores: dot([emb[neigh], h], W_mk) + b_mk (len 768)
      for (int k = warp; k < Kk; k += 8) {
        const float* ev = sE + k * 256;
        float acc = 0.0f;
        for (int i = lane; i < Ek + Dk; i += 32) {
          float v = (i < Ek) ? ev[i] : hb[i - Ek];
          acc = fmaf(v, W_mk[i], acc);
        }
        for (int o = 16; o; o >>= 1) acc += __shfl_down_sync(0xffffffffu, acc, o);
        if (lane == 0) s_score[k] = __fadd_rn(acc, b_mk[0]);
      }

      float newt = 0.0f;
      if (tid == 0) {
        float s = red[0];
        for (int w = 1; w < 8; w++) s = __fadd_rn(s, red[w]);
        float xx = __fadd_rn(s, b_time[0]);
        float sp = __fadd_rn(fmaxf(xx, 0.0f), log1pf(expf(-fabsf(xx))));
        newt = __fadd_rn(g_last_t[myb], sp);
      }
      __syncthreads();

      if (tid == 0) {
        float mx = s_score[0];
        for (int k = 1; k < Kk; k++) mx = fmaxf(mx, s_score[k]);
        float ee[Kk]; float ssum = 0.0f;
        for (int k = 0; k < Kk; k++) {
          ee[k] = expf(__fadd_rn(s_score[k], -mx));
          ssum = __fadd_rn(ssum, ee[k]);
        }
        float cp = sP[chosen];
        sP[chosen] = __fmul_rn(cp, __fdiv_rn(ee[0], ssum));
        int base = 1 + t * (Kk - 1);
        for (int k = 1; k < Kk; k++) {
          sP[base + k - 1] = __fmul_rn(cp, __fdiv_rn(ee[k], ssum));
          sC[base + k - 1] = s_neigh[k];
        }
      }
      __syncthreads();

      // gumbel-max over the active prefix (prob==0 beyond -> exactly -1e30)
      uint32_t k0, k1;
      tf2x32(0u, 42u, 0u, (uint32_t)t, k0, k1);
      int active = 15 * t + 16;
      if (active > Lk) active = Lk;
      float bv = -3.4e38f; int bi = 0x7fffffff;
      for (int l = tid; l < active; l += 256) {
        float pr = sP[l];
        float logit = (pr > 0.0f) ? logf(fmaxf(pr, 1e-38f)) : -1e30f;
        uint32_t i = (uint32_t)(myb * Lk + l);
        uint32_t o0, o1;
        tf2x32(k0, k1, 0u, i, o0, o1);
        uint32_t bits = o0 ^ o1;
        float u0 = __fadd_rn(__uint_as_float((bits >> 9) | 0x3f800000u), -1.0f);
        float u = fmaxf(TINYF, __fadd_rn(u0, TINYF));
        float gq = -logf(-logf(u));
        float v = __fadd_rn(logit, gq);
        if (v > bv) { bv = v; bi = l; }
      }
      for (int o = 16; o; o >>= 1) {
        float ov = __shfl_down_sync(0xffffffffu, bv, o);
        int   oi = __shfl_down_sync(0xffffffffu, bi, o);
        if (ov > bv || (ov == bv && oi < bi)) { bv = ov; bi = oi; }
      }
      if (lane == 0) { redv[warp] = bv; ri[warp] = bi; }
      __syncthreads();

      // all threads compute besti (keeps `chosen` uniform without broadcast)
      float bestv = redv[0]; int besti = ri[0];
      for (int w = 1; w < 8; w++) {
        if (redv[w] > bestv || (redv[w] == bestv && ri[w] < besti)) {
          bestv = redv[w]; besti = ri[w];
        }
      }
      chosen = besti;
      if (tid == 0) {
        int nm = sC[besti];
        float snp = sN[besti];
        float ssp = sP[besti];
        int col = t + 1;
        out[0 * 16384 + myb * Sk + col] = (float)nm;
        out[1 * 16384 + myb * Sk + col] = newt;
        out[2 * 16384 + myb * Sk + col] = (newt < 1000.0f) ? 1.0f : 0.0f;
        out[3 * 16384 + myb * Sk + col] = snp;
        out[4 * 16384 + myb * Sk + col] = ssp;
        g_last_m[myb] = nm;
        g_last_t[myb] = newt;
      }
    }
    gbar(bc, epoch);
  }
}

extern "C" void kernel_launch(void* const* d_in, const int* in_sizes, int n_in,
                              void* d_out, int out_size) {
  const int*   marker = (const int*)d_in[0];
  const float* timed  = (const float*)d_in[1];
  const float* maskd  = (const float*)d_in[2];
  const float* emb    = (const float*)d_in[3];
  const int*   nlist  = (const int*)d_in[4];
  const float* nprob  = (const float*)d_in[5];
  const float* W_te   = (const float*)d_in[6];
  const float* b_te   = (const float*)d_in[7];
  const float* W_el   = (const float*)d_in[8];
  const float* b_el   = (const float*)d_in[9];
  const float* W_ih   = (const float*)d_in[10];
  const float* b_ih   = (const float*)d_in[11];
  const float* W_hh   = (const float*)d_in[12];
  const float* b_hh   = (const float*)d_in[13];
  const float* W_time = (const float*)d_in[14];
  const float* b_time = (const float*)d_in[15];
  const float* W_mk   = (const float*)d_in[16];
  const float* b_mk   = (const float*)d_in[17];
  float* out = (float*)d_out;

  cudaFuncSetAttribute(rnn_persistent,
                       cudaFuncAttributeMaxDynamicSharedMemorySize, SM_BYTES);
  reset_kernel<<<1, 128>>>();
  rnn_persistent<<<128, 256, SM_BYTES>>>(marker, timed, maskd, emb, nlist, nprob,
                                         W_te, b_te, W_el, b_el, W_ih, b_ih,
                                         W_hh, b_hh, W_time, b_time, W_mk, b_mk,
                                         out);
}

// round 7
// speedup vs baseline: 4.0122x; 1.3368x over previous
#include <cuda_runtime.h>
#include <cstdint>

#define Bk 128
#define Sk 128
#define Ek 256
#define Dk 512
#define Kk 16
#define Lk 1906
#define Rk 2033
#define Tk 127
#define TINYF 1.17549435e-38f

// smem layout (float offsets)
#define OFF_ST    0        // staging 32x516 (B), vec 32x260 (A), C scratch
#define OFF_WA    16512    // W_el tile: 256e x 8dp float2
#define OFF_WBI   20608    // 8dp x 514 float2
#define OFF_WBH   28832
#define OFF_SE    37056    // 16x256 neighbor emb
#define OFF_WMK   41152    // 768
#define OFF_WTM   41920    // 512
#define OFF_WTE   42432    // 256
#define OFF_BTE   42688    // 256
#define OFF_BEL   42944    // 512
#define OFF_BIH   43456    // 512
#define OFF_BHH   43968    // 512
#define OFF_BT    44480    // b_time, b_mk
#define OFF_SLT   44484    // 32
#define OFF_SLM   44516    // 32
#define OFF_CS    44548    // red8, redv8, ri8, neigh16, score16
#define SM_FLOATS 44616
#define SM_BYTES  (SM_FLOATS * 4)

__device__ float g_h[2][Bk][Dk];
__device__ float g_x[Bk][Dk];
__device__ float g_last_t[Bk];
__device__ int   g_last_m[Bk];
__device__ float g_prob[Bk][Lk];
__device__ int   g_cand[Bk][Lk];
__device__ float g_nrec[Bk][Rk];
__device__ unsigned g_cnt[4][32];   // per-group counters, 128B apart

// JAX threefry2x32 (exact)
__device__ __forceinline__ void tf2x32(uint32_t k0, uint32_t k1,
                                       uint32_t x0, uint32_t x1,
                                       uint32_t& o0, uint32_t& o1) {
  uint32_t ks2 = k0 ^ k1 ^ 0x1BD11BDAu;
  x0 += k0; x1 += k1;
#define RR(d) { x0 += x1; x1 = (x1 << d) | (x1 >> (32 - d)); x1 ^= x0; }
  RR(13) RR(15) RR(26) RR(6)  x0 += k1;  x1 += ks2 + 1u;
  RR(17) RR(29) RR(16) RR(24) x0 += ks2; x1 += k0 + 2u;
  RR(13) RR(15) RR(26) RR(6)  x0 += k0;  x1 += k1 + 3u;
  RR(17) RR(29) RR(16) RR(24) x0 += k1;  x1 += ks2 + 4u;
  RR(13) RR(15) RR(26) RR(6)  x0 += ks2; x1 += k0 + 5u;
#undef RR
  o0 = x0; o1 = x1;
}

__device__ __forceinline__ unsigned long long dup2(float v) {
  unsigned long long r;
  asm("mov.b64 %0, {%1, %1};" : "=l"(r) : "f"(v));
  return r;
}
__device__ __forceinline__ void ffma2(unsigned long long& acc,
                                      unsigned long long a,
                                      unsigned long long b) {
  asm("fma.rn.f32x2 %0, %1, %2, %3;" : "=l"(acc) : "l"(a), "l"(b), "l"(acc));
}
__device__ __forceinline__ void cpa16(uint32_t s, const void* g) {
  asm volatile("cp.async.cg.shared.global [%0], [%1], 16;"
               :: "r"(s), "l"(g) : "memory");
}
__device__ __forceinline__ void cpa_wait_all() {
  asm volatile("cp.async.wait_all;" ::: "memory");
}

__global__ void reset_kernel() {
  if (threadIdx.x < 128) ((unsigned*)g_cnt)[threadIdx.x] = 0u;
}

// fence-free group barrier: release-red arrive + volatile poll
__device__ __forceinline__ void gbar(int bc, unsigned& epoch) {
  __syncthreads();
  if (threadIdx.x == 0) {
    epoch += 32u;
    asm volatile("red.release.gpu.global.add.u32 [%0], %1;"
                 :: "l"(&g_cnt[bc][0]), "r"(1u) : "memory");
    while (*((volatile unsigned*)&g_cnt[bc][0]) < epoch) { }
  }
  __syncthreads();
}

__global__ void __launch_bounds__(256, 1)
rnn_persistent(const int* __restrict__ marker,
               const float* __restrict__ timed,
               const float* __restrict__ maskd,
               const float* __restrict__ emb,
               const int* __restrict__ nlist,
               const float* __restrict__ nprob,
               const float* __restrict__ W_te,
               const float* __restrict__ b_te,
               const float* __restrict__ W_el,
               const float* __restrict__ b_el,
               const float* __restrict__ W_ih,
               const float* __restrict__ b_ih,
               const float* __restrict__ W_hh,
               const float* __restrict__ b_hh,
               const float* __restrict__ W_time,
               const float* __restrict__ b_time,
               const float* __restrict__ W_mk,
               const float* __restrict__ b_mk,
               float* __restrict__ out) {
  extern __shared__ __align__(16) float SM[];
  const int BID = blockIdx.x;
  if (BID >= 128) return;            // grid padded to 148 (throttle probe)
  const int tid = threadIdx.x;
  const int bc = BID >> 5;           // group (32 batch rows)
  const int dc = BID & 31;           // d tile (16 cols)
  const int myb = BID;               // phase-C row (= bc*32 + dc)
  unsigned epoch = 0;

  // ---------------- one-time init ----------------
  for (int i = tid; i < Ek * 8; i += 256) {
    int e = i >> 3, dp8 = i & 7;
    ((float2*)(SM + OFF_WA))[e * 8 + dp8] =
        *(const float2*)&W_el[e * Dk + dc * 16 + dp8 * 2];
  }
  for (int i = tid; i < Dk * 8; i += 256) {
    int e = i >> 3, dp8 = i & 7;
    ((float2*)(SM + OFF_WBI))[dp8 * 514 + e] =
        *(const float2*)&W_ih[e * Dk + dc * 16 + dp8 * 2];
    ((float2*)(SM + OFF_WBH))[dp8 * 514 + e] =
        *(const float2*)&W_hh[e * Dk + dc * 16 + dp8 * 2];
  }
  for (int i = tid; i < Ek + Dk; i += 256) SM[OFF_WMK + i] = W_mk[i];
  for (int i = tid; i < Dk; i += 256) {
    SM[OFF_WTM + i] = W_time[i];
    SM[OFF_BEL + i] = b_el[i];
    SM[OFF_BIH + i] = b_ih[i];
    SM[OFF_BHH + i] = b_hh[i];
  }
  if (tid < Ek) { SM[OFF_WTE + tid] = W_te[tid]; SM[OFF_BTE + tid] = b_te[tid]; }
  if (tid == 0) { SM[OFF_BT] = b_time[0]; SM[OFF_BT + 1] = b_mk[0]; }

  for (int l = tid; l < Lk; l += 256) {
    g_prob[myb][l] = (l == 0) ? 1.0f : 0.0f;
    g_cand[myb][l] = (l == 0) ? marker[myb * Sk] : 0;
  }
  for (int r = tid; r < Rk; r += 256) g_nrec[myb][r] = 1.0f;
  for (int d = tid; d < Dk; d += 256) __stcg(&g_h[0][myb][d], 0.0f);
  int chosen = 0;
  if (tid == 0) {
    __stcg(&g_last_t[myb], timed[myb * Sk]);
    __stcg(&g_last_m[myb], marker[myb * Sk]);
    out[0 * 16384 + myb * Sk] = (float)marker[myb * Sk];
    out[1 * 16384 + myb * Sk] = timed[myb * Sk];
    out[2 * 16384 + myb * Sk] = maskd[myb * Sk];
    out[3 * 16384 + myb * Sk] = 1.0f;
    out[4 * 16384 + myb * Sk] = 1.0f;
  }
  gbar(bc, epoch);

  const int dp = tid & 7;
  const int blw = tid >> 3;          // 0..31
  const int d0 = dc * 16 + dp * 2;
  const int bg = bc * 32 + blw;
  int*   s_neigh = (int*)(SM + OFF_CS + 24);
  float* s_score = SM + OFF_CS + 40;
  const uint32_t st_base = (uint32_t)__cvta_generic_to_shared(SM + OFF_ST);
  const uint32_t se_base = (uint32_t)__cvta_generic_to_shared(SM + OFF_SE);

  for (int t = 0; t < Tk; t++) {
    // ============ Phase A: x = leaky(vec @ W_el + b_el) ============
    {
      if (tid < 32) {
        SM[OFF_SLT + tid] = __ldcg(&g_last_t[bc * 32 + tid]);
        ((int*)(SM + OFF_SLM))[tid] = __ldcg(&g_last_m[bc * 32 + tid]);
      }
      __syncthreads();
      // stage 32 emb rows via cp.async (raw), 8 x 16B per thread
#pragma unroll
      for (int j = 0; j < 8; j++) {
        int id = tid + j * 256;
        int bl = id >> 6, seg = id & 63;
        cpa16(st_base + (uint32_t)(bl * 260 + seg * 4) * 4,
              emb + (size_t)((int*)(SM + OFF_SLM))[bl] * Ek + seg * 4);
      }
      cpa_wait_all();
      __syncthreads();
      // in-place: vec = raw + 0.1*(lt*wte + bte), thread owns column e=tid
      {
        float wte = SM[OFF_WTE + tid], bte = SM[OFF_BTE + tid];
        float* sV = SM + OFF_ST;
#pragma unroll 4
        for (int bl = 0; bl < 32; bl++) {
          float te = __fadd_rn(__fmul_rn(SM[OFF_SLT + bl], wte), bte);
          sV[bl * 260 + tid] = __fadd_rn(sV[bl * 260 + tid], __fmul_rn(0.1f, te));
        }
      }
      __syncthreads();
      const float* pv = SM + OFF_ST + blw * 260;
      const float2* wa = (const float2*)(SM + OFF_WA);
      float a0 = 0.0f, a1 = 0.0f;
#pragma unroll 8
      for (int e = 0; e < Ek; e++) {
        float v = pv[e];
        float2 w = wa[e * 8 + dp];
        a0 = fmaf(v, w.x, a0);
        a1 = fmaf(v, w.y, a1);
      }
      a0 = __fadd_rn(a0, SM[OFF_BEL + d0]);
      a1 = __fadd_rn(a1, SM[OFF_BEL + d0 + 1]);
      float2 r;
      r.x = (a0 >= 0.0f) ? a0 : __fmul_rn(0.01f, a0);
      r.y = (a1 >= 0.0f) ? a1 : __fmul_rn(0.01f, a1);
      __stcg((float2*)&g_x[bg][d0], r);

      // prefetch C's neighbor rows (overlaps all of phase B)
      int lm_my = ((int*)(SM + OFF_SLM))[dc];
      if (tid < Kk) {
        s_neigh[tid] = nlist[lm_my * Kk + tid];
        g_nrec[myb][1 + t * Kk + tid] = nprob[lm_my * Kk + tid];
      }
      __syncthreads();
#pragma unroll
      for (int j = 0; j < 4; j++) {
        int id = tid + j * 256;
        int k = id >> 6, seg = id & 63;
        cpa16(se_base + (uint32_t)(k * 256 + seg * 4) * 4,
              emb + (size_t)s_neigh[k] * Ek + seg * 4);
      }
    }
    gbar(bc, epoch);

    // ============ Phase B: h = tanh(x@W_ih + b_ih + h@W_hh + b_hh) ============
    {
      unsigned long long axx = 0ull, ahh = 0ull;
      // ---- x pass ----
#pragma unroll
      for (int j = 0; j < 16; j++) {
        int id = tid + j * 256;
        int r = id >> 7, seg = id & 127;
        cpa16(st_base + (uint32_t)(r * 516 + seg * 4) * 4,
              &g_x[bc * 32 + r][seg * 4]);
      }
      cpa_wait_all();   // also drains sE prefetch (issued long ago)
      __syncthreads();
      {
        const float4* px = (const float4*)(SM + OFF_ST + blw * 516);
        const ulonglong2* pwi = (const ulonglong2*)(SM + OFF_WBI) + dp * 257;
#pragma unroll 8
        for (int e4 = 0; e4 < 128; e4++) {
          float4 xq = px[e4];
          ulonglong2 wA = pwi[2 * e4], wB = pwi[2 * e4 + 1];
          ffma2(axx, dup2(xq.x), wA.x);
          ffma2(axx, dup2(xq.y), wA.y);
          ffma2(axx, dup2(xq.z), wB.x);
          ffma2(axx, dup2(xq.w), wB.y);
        }
      }
      __syncthreads();
      // ---- h pass (reuse buffer) ----
      const float* hin = &g_h[t & 1][0][0];
#pragma unroll
      for (int j = 0; j < 16; j++) {
        int id = tid + j * 256;
        int r = id >> 7, seg = id & 127;
        cpa16(st_base + (uint32_t)(r * 516 + seg * 4) * 4,
              &hin[(bc * 32 + r) * Dk + seg * 4]);
      }
      cpa_wait_all();
      __syncthreads();
      {
        const float4* ph = (const float4*)(SM + OFF_ST + blw * 516);
        const ulonglong2* pwh = (const ulonglong2*)(SM + OFF_WBH) + dp * 257;
#pragma unroll 8
        for (int e4 = 0; e4 < 128; e4++) {
          float4 hq = ph[e4];
          ulonglong2 wA = pwh[2 * e4], wB = pwh[2 * e4 + 1];
          ffma2(ahh, dup2(hq.x), wA.x);
          ffma2(ahh, dup2(hq.y), wA.y);
          ffma2(ahh, dup2(hq.z), wB.x);
          ffma2(ahh, dup2(hq.w), wB.y);
        }
      }
      float ax0, ax1, ah0, ah1;
      asm("mov.b64 {%0, %1}, %2;" : "=f"(ax0), "=f"(ax1) : "l"(axx));
      asm("mov.b64 {%0, %1}, %2;" : "=f"(ah0), "=f"(ah1) : "l"(ahh));
      float2 r;
      r.x = tanhf(__fadd_rn(__fadd_rn(__fadd_rn(ax0, SM[OFF_BIH + d0]), ah0),
                            SM[OFF_BHH + d0]));
      r.y = tanhf(__fadd_rn(__fadd_rn(__fadd_rn(ax1, SM[OFF_BIH + d0 + 1]), ah1),
                            SM[OFF_BHH + d0 + 1]));
      __stcg((float2*)&g_h[(t + 1) & 1][bg][d0], r);
    }
    gbar(bc, epoch);

    // ============ Phase C: sampling step for row myb ============
    {
      float* hb   = SM + OFF_ST;            // [512]
      float* red  = SM + OFF_CS;            // [8]
      float* redv = SM + OFF_CS + 8;        // [8]
      int*   ri   = (int*)(SM + OFF_CS + 16);
      float* sE   = SM + OFF_SE;
      int warp = tid >> 5, lane = tid & 31;

      hb[tid]       = __ldcg(&g_h[(t + 1) & 1][myb][tid]);
      hb[tid + 256] = __ldcg(&g_h[(t + 1) & 1][myb][tid + 256]);
      __syncthreads();

      // dt partial + warp reduce
      {
        float a = __fmul_rn(hb[2 * tid], SM[OFF_WTM + 2 * tid]);
        a = fmaf(hb[2 * tid + 1], SM[OFF_WTM + 2 * tid + 1], a);
        for (int o = 16; o; o >>= 1)
          a = __fadd_rn(a, __shfl_down_sync(0xffffffffu, a, o));
        if (lane == 0) red[warp] = a;
      }
      __syncthreads();

      // neighbor scores: dot([emb[neigh], h], W_mk) + b_mk (len 768)
      for (int k = warp; k < Kk; k += 8) {
        const float* ev = sE + k * 256;
        float acc = 0.0f;
        for (int i = lane; i < Ek + Dk; i += 32) {
          float v = (i < Ek) ? ev[i] : hb[i - Ek];
          acc = fmaf(v, SM[OFF_WMK + i], acc);
        }
        for (int o = 16; o; o >>= 1) acc += __shfl_down_sync(0xffffffffu, acc, o);
        if (lane == 0) s_score[k] = __fadd_rn(acc, SM[OFF_BT + 1]);
      }

      float newt = 0.0f;
      if (tid == 0) {
        float s = red[0];
        for (int w = 1; w < 8; w++) s = __fadd_rn(s, red[w]);
        float xx = __fadd_rn(s, SM[OFF_BT]);
        float sp = __fadd_rn(fmaxf(xx, 0.0f), log1pf(expf(-fabsf(xx))));
        newt = __fadd_rn(__ldcg(&g_last_t[myb]), sp);
      }
      __syncthreads();

      if (tid == 0) {
        float mx = s_score[0];
        for (int k = 1; k < Kk; k++) mx = fmaxf(mx, s_score[k]);
        float ee[Kk]; float ssum = 0.0f;
        for (int k = 0; k < Kk; k++) {
          ee[k] = expf(__fadd_rn(s_score[k], -mx));
          ssum = __fadd_rn(ssum, ee[k]);
        }
        float cp = g_prob[myb][chosen];
        g_prob[myb][chosen] = __fmul_rn(cp, __fdiv_rn(ee[0], ssum));
        int base = 1 + t * (Kk - 1);
        for (int k = 1; k < Kk; k++) {
          g_prob[myb][base + k - 1] = __fmul_rn(cp, __fdiv_rn(ee[k], ssum));
          g_cand[myb][base + k - 1] = s_neigh[k];
        }
      }
      __syncthreads();

      // gumbel-max over the active prefix (prob==0 beyond -> exactly -1e30)
      uint32_t k0, k1;
      tf2x32(0u, 42u, 0u, (uint32_t)t, k0, k1);
      int active = 15 * t + 16;
      if (active > Lk) active = Lk;
      float bv = -3.4e38f; int bi = 0x7fffffff;
      for (int l = tid; l < active; l += 256) {
        float pr = g_prob[myb][l];
        float logit = (pr > 0.0f) ? logf(fmaxf(pr, 1e-38f)) : -1e30f;
        uint32_t i = (uint32_t)(myb * Lk + l);
        uint32_t o0, o1;
        tf2x32(k0, k1, 0u, i, o0, o1);
        uint32_t bits = o0 ^ o1;
        float u0 = __fadd_rn(__uint_as_float((bits >> 9) | 0x3f800000u), -1.0f);
        float u = fmaxf(TINYF, __fadd_rn(u0, TINYF));
        float gq = -logf(-logf(u));
        float v = __fadd_rn(logit, gq);
        if (v > bv) { bv = v; bi = l; }
      }
      for (int o = 16; o; o >>= 1) {
        float ov = __shfl_down_sync(0xffffffffu, bv, o);
        int   oi = __shfl_down_sync(0xffffffffu, bi, o);
        if (ov > bv || (ov == bv && oi < bi)) { bv = ov; bi = oi; }
      }
      if (lane == 0) { redv[warp] = bv; ri[warp] = bi; }
      __syncthreads();

      float bestv = redv[0]; int besti = ri[0];
      for (int w = 1; w < 8; w++) {
        if (redv[w] > bestv || (redv[w] == bestv && ri[w] < besti)) {
          bestv = redv[w]; besti = ri[w];
        }
      }
      chosen = besti;
      if (tid == 0) {
        int nm = g_cand[myb][besti];
        float snp = g_nrec[myb][besti];
        float ssp = g_prob[myb][besti];
        int col = t + 1;
        out[0 * 16384 + myb * Sk + col] = (float)nm;
        out[1 * 16384 + myb * Sk + col] = newt;
        out[2 * 16384 + myb * Sk + col] = (newt < 1000.0f) ? 1.0f : 0.0f;
        out[3 * 16384 + myb * Sk + col] = snp;
        out[4 * 16384 + myb * Sk + col] = ssp;
        __stcg(&g_last_m[myb], nm);
        __stcg(&g_last_t[myb], newt);
      }
    }
    gbar(bc, epoch);
  }
}

extern "C" void kernel_launch(void* const* d_in, const int* in_sizes, int n_in,
                              void* d_out, int out_size) {
  const int*   marker = (const int*)d_in[0];
  const float* timed  = (const float*)d_in[1];
  const float* maskd  = (const float*)d_in[2];
  const float* emb    = (const float*)d_in[3];
  const int*   nlist  = (const int*)d_in[4];
  const float* nprob  = (const float*)d_in[5];
  const float* W_te   = (const float*)d_in[6];
  const float* b_te   = (const float*)d_in[7];
  const float* W_el   = (const float*)d_in[8];
  const float* b_el   = (const float*)d_in[9];
  const float* W_ih   = (const float*)d_in[10];
  const float* b_ih   = (const float*)d_in[11];
  const float* W_hh   = (const float*)d_in[12];
  const float* b_hh   = (const float*)d_in[13];
  const float* W_time = (const float*)d_in[14];
  const float* b_time = (const float*)d_in[15];
  const float* W_mk   = (const float*)d_in[16];
  const float* b_mk   = (const float*)d_in[17];
  float* out = (float*)d_out;

  cudaFuncSetAttribute(rnn_persistent,
                       cudaFuncAttributeMaxDynamicSharedMemorySize, SM_BYTES);
  reset_kernel<<<1, 128>>>();
  rnn_persistent<<<148, 256, SM_BYTES>>>(marker, timed, maskd, emb, nlist, nprob,
                                         W_te, b_te, W_el, b_el, W_ih, b_ih,
                                         W_hh, b_hh, W_time, b_time, W_mk, b_mk,
                                         out);
}

// round 8
// speedup vs baseline: 4.2024x; 1.0474x over previous
#include <cuda_runtime.h>
#include <cstdint>

#define Bk 128
#define Sk 128
#define Ek 256
#define Dk 512
#define Kk 16
#define Lk 1906
#define Rk 2033
#define Tk 127
#define TINYF 1.17549435e-38f

// smem layout (float offsets)
#define OFF_STA   0        // buffer A: 32x260
#define OFF_STB   8320     // buffer B: 32x260
#define OFF_WA    16640    // W_el tile: 256e x 8dp float2
#define OFF_WBI   20736    // 8dp x 514 float2
#define OFF_WBH   28960
#define OFF_SE    37184    // 16x256 neighbor emb
#define OFF_WMK   41280    // 768
#define OFF_WTM   42048    // 512
#define OFF_WTE   42560    // 256
#define OFF_BTE   42816    // 256
#define OFF_BEL   43072    // 512
#define OFF_BIH   43584    // 512
#define OFF_BHH   44096    // 512
#define OFF_BT    44608    // b_time, b_mk, last_t_my
#define OFF_SLT   44612    // 32
#define OFF_SLM   44644    // 32
#define OFF_CS    44676    // red8, redv8, ri8, neigh16, score16
#define OFF_SP    44740    // prob[1906]
#define OFF_SC    46646    // cand[1906] (int)
#define OFF_SN    48552    // nrec[2033]
#define SM_FLOATS 50592
#define SM_BYTES  (SM_FLOATS * 4)

__device__ float g_h[2][Bk][Dk];
__device__ float g_x[Bk][Dk];
__device__ float g_last_t[Bk];
__device__ int   g_last_m[Bk];
__device__ unsigned g_cnt[4][32];   // per-group counters, 128B apart

// JAX threefry2x32 (exact)
__device__ __forceinline__ void tf2x32(uint32_t k0, uint32_t k1,
                                       uint32_t x0, uint32_t x1,
                                       uint32_t& o0, uint32_t& o1) {
  uint32_t ks2 = k0 ^ k1 ^ 0x1BD11BDAu;
  x0 += k0; x1 += k1;
#define RR(d) { x0 += x1; x1 = (x1 << d) | (x1 >> (32 - d)); x1 ^= x0; }
  RR(13) RR(15) RR(26) RR(6)  x0 += k1;  x1 += ks2 + 1u;
  RR(17) RR(29) RR(16) RR(24) x0 += ks2; x1 += k0 + 2u;
  RR(13) RR(15) RR(26) RR(6)  x0 += k0;  x1 += k1 + 3u;
  RR(17) RR(29) RR(16) RR(24) x0 += k1;  x1 += ks2 + 4u;
  RR(13) RR(15) RR(26) RR(6)  x0 += ks2; x1 += k0 + 5u;
#undef RR
  o0 = x0; o1 = x1;
}

__device__ __forceinline__ unsigned long long dup2(float v) {
  unsigned long long r;
  asm("mov.b64 %0, {%1, %1};" : "=l"(r) : "f"(v));
  return r;
}
__device__ __forceinline__ void ffma2(unsigned long long& acc,
                                      unsigned long long a,
                                      unsigned long long b) {
  asm("fma.rn.f32x2 %0, %1, %2, %3;" : "=l"(acc) : "l"(a), "l"(b), "l"(acc));
}
__device__ __forceinline__ void cpa16(uint32_t s, const void* g) {
  asm volatile("cp.async.cg.shared.global [%0], [%1], 16;"
               :: "r"(s), "l"(g) : "memory");
}
__device__ __forceinline__ void cpa_commit() {
  asm volatile("cp.async.commit_group;" ::: "memory");
}
template <int N>
__device__ __forceinline__ void cpa_wait_group() {
  asm volatile("cp.async.wait_group %0;" :: "n"(N) : "memory");
}

__global__ void reset_kernel() {
  if (threadIdx.x < 128) ((unsigned*)g_cnt)[threadIdx.x] = 0u;
}

// fence-free group barrier: release-red arrive + volatile poll
__device__ __forceinline__ void gbar(int bc, unsigned& epoch) {
  __syncthreads();
  if (threadIdx.x == 0) {
    epoch += 32u;
    asm volatile("red.release.gpu.global.add.u32 [%0], %1;"
                 :: "l"(&g_cnt[bc][0]), "r"(1u) : "memory");
    while (*((volatile unsigned*)&g_cnt[bc][0]) < epoch) { }
  }
  __syncthreads();
}

__global__ void __launch_bounds__(256, 1)
rnn_persistent(const int* __restrict__ marker,
               const float* __restrict__ timed,
               const float* __restrict__ maskd,
               const float* __restrict__ emb,
               const int* __restrict__ nlist,
               const float* __restrict__ nprob,
               const float* __restrict__ W_te,
               const float* __restrict__ b_te,
               const float* __restrict__ W_el,
               const float* __restrict__ b_el,
               const float* __restrict__ W_ih,
               const float* __restrict__ b_ih,
               const float* __restrict__ W_hh,
               const float* __restrict__ b_hh,
               const float* __restrict__ W_time,
               const float* __restrict__ b_time,
               const float* __restrict__ W_mk,
               const float* __restrict__ b_mk,
               float* __restrict__ out) {
  extern __shared__ __align__(16) float SM[];
  const int BID = blockIdx.x;
  if (BID >= 128) return;
  const int tid = threadIdx.x;
  const int bc = BID >> 5;           // group (32 batch rows)
  const int dc = BID & 31;           // d tile (16 cols)
  const int myb = BID;               // phase-C row
  unsigned epoch = 0;

  float* sP = SM + OFF_SP;
  int*   sC = (int*)(SM + OFF_SC);
  float* sN = SM + OFF_SN;

  // ---------------- one-time init ----------------
  for (int i = tid; i < Ek * 8; i += 256) {
    int e = i >> 3, dp8 = i & 7;
    ((float2*)(SM + OFF_WA))[e * 8 + dp8] =
        *(const float2*)&W_el[e * Dk + dc * 16 + dp8 * 2];
  }
  for (int i = tid; i < Dk * 8; i += 256) {
    int e = i >> 3, dp8 = i & 7;
    ((float2*)(SM + OFF_WBI))[dp8 * 514 + e] =
        *(const float2*)&W_ih[e * Dk + dc * 16 + dp8 * 2];
    ((float2*)(SM + OFF_WBH))[dp8 * 514 + e] =
        *(const float2*)&W_hh[e * Dk + dc * 16 + dp8 * 2];
  }
  for (int i = tid; i < Ek + Dk; i += 256) SM[OFF_WMK + i] = W_mk[i];
  for (int i = tid; i < Dk; i += 256) {
    SM[OFF_WTM + i] = W_time[i];
    SM[OFF_BEL + i] = b_el[i];
    SM[OFF_BIH + i] = b_ih[i];
    SM[OFF_BHH + i] = b_hh[i];
  }
  if (tid < Ek) { SM[OFF_WTE + tid] = W_te[tid]; SM[OFF_BTE + tid] = b_te[tid]; }
  if (tid == 0) {
    SM[OFF_BT] = b_time[0]; SM[OFF_BT + 1] = b_mk[0];
    SM[OFF_BT + 2] = timed[myb * Sk];        // last_t (own row)
  }
  for (int l = tid; l < Lk; l += 256) {
    sP[l] = (l == 0) ? 1.0f : 0.0f;
    sC[l] = (l == 0) ? marker[myb * Sk] : 0;
  }
  for (int r = tid; r < Rk; r += 256) sN[r] = 1.0f;
  for (int d = tid; d < Dk; d += 256) __stcg(&g_h[0][myb][d], 0.0f);
  int chosen = 0;
  if (tid == 0) {
    __stcg(&g_last_t[myb], timed[myb * Sk]);
    __stcg(&g_last_m[myb], marker[myb * Sk]);
    out[0 * 16384 + myb * Sk] = (float)marker[myb * Sk];
    out[1 * 16384 + myb * Sk] = timed[myb * Sk];
    out[2 * 16384 + myb * Sk] = maskd[myb * Sk];
    out[3 * 16384 + myb * Sk] = 1.0f;
    out[4 * 16384 + myb * Sk] = 1.0f;
  }
  gbar(bc, epoch);

  const int dp = tid & 7;
  const int blw = tid >> 3;          // 0..31
  const int d0 = dc * 16 + dp * 2;
  const int bg = bc * 32 + blw;
  int*   s_neigh = (int*)(SM + OFF_CS + 24);
  float* s_score = SM + OFF_CS + 40;
  const uint32_t stA = (uint32_t)__cvta_generic_to_shared(SM + OFF_STA);
  const uint32_t stB = (uint32_t)__cvta_generic_to_shared(SM + OFF_STB);
  const uint32_t se_base = (uint32_t)__cvta_generic_to_shared(SM + OFF_SE);
  const int r_st = tid >> 3;         // 0..31, row per thread for staging
  const int seg_st = tid & 7;        // 8 segs x 16B = 128B per row-chunk? no:
  // staging helper indices: 32 rows x 64 16B-segs = 2048 units; 8 per thread

  for (int t = 0; t < Tk; t++) {
    // ============ Phase A: x = leaky(vec @ W_el + b_el) ============
    {
      if (tid < 32) {
        SM[OFF_SLT + tid] = __ldcg(&g_last_t[bc * 32 + tid]);
        ((int*)(SM + OFF_SLM))[tid] = __ldcg(&g_last_m[bc * 32 + tid]);
      }
      __syncthreads();
      // stage 32 emb rows into bufA
#pragma unroll
      for (int j = 0; j < 8; j++) {
        int id = tid + j * 256;
        int bl = id >> 6, seg = id & 63;
        cpa16(stA + (uint32_t)(bl * 260 + seg * 4) * 4,
              emb + (size_t)((int*)(SM + OFF_SLM))[bl] * Ek + seg * 4);
      }
      cpa_commit();
      cpa_wait_group<0>();
      __syncthreads();
      {
        float wte = SM[OFF_WTE + tid], bte = SM[OFF_BTE + tid];
        float* sV = SM + OFF_STA;
#pragma unroll 4
        for (int bl = 0; bl < 32; bl++) {
          float te = __fadd_rn(__fmul_rn(SM[OFF_SLT + bl], wte), bte);
          sV[bl * 260 + tid] = __fadd_rn(sV[bl * 260 + tid], __fmul_rn(0.1f, te));
        }
      }
      __syncthreads();
      const float* pv = SM + OFF_STA + blw * 260;
      const unsigned long long* wa = (const unsigned long long*)(SM + OFF_WA);
      unsigned long long acc2 = 0ull;
#pragma unroll 8
      for (int e = 0; e < Ek; e++) {
        ffma2(acc2, dup2(pv[e]), wa[e * 8 + dp]);
      }
      float a0, a1;
      asm("mov.b64 {%0, %1}, %2;" : "=f"(a0), "=f"(a1) : "l"(acc2));
      a0 = __fadd_rn(a0, SM[OFF_BEL + d0]);
      a1 = __fadd_rn(a1, SM[OFF_BEL + d0 + 1]);
      float2 r;
      r.x = (a0 >= 0.0f) ? a0 : __fmul_rn(0.01f, a0);
      r.y = (a1 >= 0.0f) ? a1 : __fmul_rn(0.01f, a1);
      __stcg((float2*)&g_x[bg][d0], r);

      // prefetch C's neighbor rows (overlaps phase B)
      int lm_my = ((int*)(SM + OFF_SLM))[dc];
      if (tid < Kk) {
        s_neigh[tid] = nlist[lm_my * Kk + tid];
        sN[1 + t * Kk + tid] = nprob[lm_my * Kk + tid];
      }
      __syncthreads();
#pragma unroll
      for (int j = 0; j < 4; j++) {
        int id = tid + j * 256;
        int k = id >> 6, seg = id & 63;
        cpa16(se_base + (uint32_t)(k * 256 + seg * 4) * 4,
              emb + (size_t)s_neigh[k] * Ek + seg * 4);
      }
      cpa_commit();      // SE group pending into B
    }
    gbar(bc, epoch);

    // ============ Phase B: pipelined h = tanh(x@Wih + b + h@Whh + b) ========
    {
      unsigned long long axx = 0ull, ahh = 0ull;
      const float* hin = &g_h[t & 1][0][0];

      // stage chunk macro: arr base ptr, e-base, dst smem base
#define STAGE(gptr, ebase, dst)                                           \
      {                                                                   \
        _Pragma("unroll")                                                 \
        for (int j = 0; j < 8; j++) {                                     \
          int id = tid + j * 256;                                         \
          int rr = id >> 6, seg = id & 63;                                \
          cpa16((dst) + (uint32_t)(rr * 260 + seg * 4) * 4,               \
                (gptr) + (size_t)(bc * 32 + rr) * Dk + (ebase) + seg * 4);\
        }                                                                 \
        cpa_commit();                                                     \
      }
#define CHUNK(accv, wbase, half, buf)                                     \
      {                                                                   \
        const float4* pxc = (const float4*)(SM + (buf) + blw * 260);      \
        const ulonglong2* pw =                                            \
            (const ulonglong2*)(SM + (wbase)) + dp * 257 + (half) * 128;  \
        _Pragma("unroll 8")                                               \
        for (int e4 = 0; e4 < 64; e4++) {                                 \
          float4 q = pxc[e4];                                             \
          ulonglong2 wA = pw[2 * e4], wB = pw[2 * e4 + 1];                \
          ffma2(accv, dup2(q.x), wA.x);                                   \
          ffma2(accv, dup2(q.y), wA.y);                                   \
          ffma2(accv, dup2(q.z), wB.x);                                   \
          ffma2(accv, dup2(q.w), wB.y);                                   \
        }                                                                 \
      }

      STAGE(&g_x[0][0], 0, stA)        // groups: [SE, x0]
      STAGE(&g_x[0][0], 256, stB)      // [SE, x0, x1]
      cpa_wait_group<1>();             // SE, x0 done
      __syncthreads();
      CHUNK(axx, OFF_WBI, 0, OFF_STA)
      __syncthreads();                 // everyone done reading bufA
      STAGE(hin, 0, stA)               // [x1, h0]
      cpa_wait_group<1>();             // x1 done
      __syncthreads();
      CHUNK(axx, OFF_WBI, 1, OFF_STB)
      __syncthreads();
      STAGE(hin, 256, stB)             // [h0, h1]
      cpa_wait_group<1>();             // h0 done
      __syncthreads();
      CHUNK(ahh, OFF_WBH, 0, OFF_STA)
      cpa_wait_group<0>();             // h1 done
      __syncthreads();
      CHUNK(ahh, OFF_WBH, 1, OFF_STB)
#undef STAGE
#undef CHUNK

      float ax0, ax1, ah0, ah1;
      asm("mov.b64 {%0, %1}, %2;" : "=f"(ax0), "=f"(ax1) : "l"(axx));
      asm("mov.b64 {%0, %1}, %2;" : "=f"(ah0), "=f"(ah1) : "l"(ahh));
      float2 r;
      r.x = tanhf(__fadd_rn(__fadd_rn(__fadd_rn(ax0, SM[OFF_BIH + d0]), ah0),
                            SM[OFF_BHH + d0]));
      r.y = tanhf(__fadd_rn(__fadd_rn(__fadd_rn(ax1, SM[OFF_BIH + d0 + 1]), ah1),
                            SM[OFF_BHH + d0 + 1]));
      __stcg((float2*)&g_h[(t + 1) & 1][bg][d0], r);
    }
    gbar(bc, epoch);

    // ============ Phase C: sampling step for row myb ============
    {
      float* hb   = SM + OFF_STA;           // [512]
      float* red  = SM + OFF_CS;            // [8]
      float* redv = SM + OFF_CS + 8;        // [8]
      int*   ri   = (int*)(SM + OFF_CS + 16);
      float* sE   = SM + OFF_SE;
      int warp = tid >> 5, lane = tid & 31;

      hb[tid]       = __ldcg(&g_h[(t + 1) & 1][myb][tid]);
      hb[tid + 256] = __ldcg(&g_h[(t + 1) & 1][myb][tid + 256]);
      __syncthreads();

      // dt partial + warp reduce
      {
        float a = __fmul_rn(hb[2 * tid], SM[OFF_WTM + 2 * tid]);
        a = fmaf(hb[2 * tid + 1], SM[OFF_WTM + 2 * tid + 1], a);
        for (int o = 16; o; o >>= 1)
          a = __fadd_rn(a, __shfl_down_sync(0xffffffffu, a, o));
        if (lane == 0) red[warp] = a;
      }
      __syncthreads();

      // neighbor scores
      for (int k = warp; k < Kk; k += 8) {
        const float* ev = sE + k * 256;
        float acc = 0.0f;
        for (int i = lane; i < Ek + Dk; i += 32) {
          float v = (i < Ek) ? ev[i] : hb[i - Ek];
          acc = fmaf(v, SM[OFF_WMK + i], acc);
        }
        for (int o = 16; o; o >>= 1) acc += __shfl_down_sync(0xffffffffu, acc, o);
        if (lane == 0) s_score[k] = __fadd_rn(acc, SM[OFF_BT + 1]);
      }

      float newt = 0.0f;
      if (tid == 0) {
        float s = red[0];
        for (int w = 1; w < 8; w++) s = __fadd_rn(s, red[w]);
        float xx = __fadd_rn(s, SM[OFF_BT]);
        float sp = __fadd_rn(fmaxf(xx, 0.0f), log1pf(expf(-fabsf(xx))));
        newt = __fadd_rn(SM[OFF_BT + 2], sp);
      }
      __syncthreads();

      // softmax + prob/cand update on warp 0 (lanes 0..15)
      if (warp == 0) {
        float sc = (lane < Kk) ? s_score[lane] : -3.4e38f;
        float mx = sc;
        for (int o = 8; o; o >>= 1)
          mx = fmaxf(mx, __shfl_xor_sync(0xffffffffu, mx, o));  // exact max
        float ek = (lane < Kk) ? expf(__fadd_rn(sc, -mx)) : 0.0f;
        // serial left-fold ssum (order-exact with reference)
        float ssum = 0.0f;
#pragma unroll
        for (int k = 0; k < Kk; k++)
          ssum = __fadd_rn(ssum, __shfl_sync(0xffffffffu, ek, k));
        float cp = sP[chosen];
        __syncwarp();
        if (lane < Kk) {
          float att = __fmul_rn(cp, __fdiv_rn(ek, ssum));
          if (lane == 0) {
            sP[chosen] = att;
          } else {
            int base = 1 + t * (Kk - 1);
            sP[base + lane - 1] = att;
            sC[base + lane - 1] = s_neigh[lane];
          }
        }
      }
      __syncthreads();

      // gumbel-max over the active prefix
      uint32_t k0, k1;
      tf2x32(0u, 42u, 0u, (uint32_t)t, k0, k1);
      int active = 15 * t + 16;
      if (active > Lk) active = Lk;
      float bv = -3.4e38f; int bi = 0x7fffffff;
      for (int l = tid; l < active; l += 256) {
        float pr = sP[l];
        float logit = (pr > 0.0f) ? logf(fmaxf(pr, 1e-38f)) : -1e30f;
        uint32_t i = (uint32_t)(myb * Lk + l);
        uint32_t o0, o1;
        tf2x32(k0, k1, 0u, i, o0, o1);
        uint32_t bits = o0 ^ o1;
        float u0 = __fadd_rn(__uint_as_float((bits >> 9) | 0x3f800000u), -1.0f);
        float u = fmaxf(TINYF, __fadd_rn(u0, TINYF));
        float gq = -logf(-logf(u));
        float v = __fadd_rn(logit, gq);
        if (v > bv) { bv = v; bi = l; }
      }
      for (int o = 16; o; o >>= 1) {
        float ov = __shfl_down_sync(0xffffffffu, bv, o);
        int   oi = __shfl_down_sync(0xffffffffu, bi, o);
        if (ov > bv || (ov == bv && oi < bi)) { bv = ov; bi = oi; }
      }
      if (lane == 0) { redv[warp] = bv; ri[warp] = bi; }
      __syncthreads();

      float bestv = redv[0]; int besti = ri[0];
      for (int w = 1; w < 8; w++) {
        if (redv[w] > bestv || (redv[w] == bestv && ri[w] < besti)) {
          bestv = redv[w]; besti = ri[w];
        }
      }
      chosen = besti;
      if (tid == 0) {
        int nm = sC[besti];
        int col = t + 1;
        out[0 * 16384 + myb * Sk + col] = (float)nm;
        out[1 * 16384 + myb * Sk + col] = newt;
        out[2 * 16384 + myb * Sk + col] = (newt < 1000.0f) ? 1.0f : 0.0f;
        out[3 * 16384 + myb * Sk + col] = sN[besti];
        out[4 * 16384 + myb * Sk + col] = sP[besti];
        SM[OFF_BT + 2] = newt;
        __stcg(&g_last_m[myb], nm);
        __stcg(&g_last_t[myb], newt);
      }
    }
    gbar(bc, epoch);
  }
}

extern "C" void kernel_launch(void* const* d_in, const int* in_sizes, int n_in,
                              void* d_out, int out_size) {
  const int*   marker = (const int*)d_in[0];
  const float* timed  = (const float*)d_in[1];
  const float* maskd  = (const float*)d_in[2];
  const float* emb    = (const float*)d_in[3];
  const int*   nlist  = (const int*)d_in[4];
  const float* nprob  = (const float*)d_in[5];
  const float* W_te   = (const float*)d_in[6];
  const float* b_te   = (const float*)d_in[7];
  const float* W_el   = (const float*)d_in[8];
  const float* b_el   = (const float*)d_in[9];
  const float* W_ih   = (const float*)d_in[10];
  const float* b_ih   = (const float*)d_in[11];
  const float* W_hh   = (const float*)d_in[12];
  const float* b_hh   = (const float*)d_in[13];
  const float* W_time = (const float*)d_in[14];
  const float* b_time = (const float*)d_in[15];
  const float* W_mk   = (const float*)d_in[16];
  const float* b_mk   = (const float*)d_in[17];
  float* out = (float*)d_out;

  cudaFuncSetAttribute(rnn_persistent,
                       cudaFuncAttributeMaxDynamicSharedMemorySize, SM_BYTES);
  reset_kernel<<<1, 128>>>();
  rnn_persistent<<<148, 256, SM_BYTES>>>(marker, timed, maskd, emb, nlist, nprob,
                                         W_te, b_te, W_el, b_el, W_ih, b_ih,
                                         W_hh, b_hh, W_time, b_time, W_mk, b_mk,
                                         out);
}